// round 12
// baseline (speedup 1.0000x reference)
#include <cuda_runtime.h>
#include <cstdint>

// LIF recurrence over 4 timesteps (forward value only):
//   mem = 0.25*mem + x[t]; spike = mem > 0.5; out[t] = spike; mem = spike ? 0 : mem
//
// x/out: [T=4, N=8388608] fp32. Fused single kernel at the HBM streaming
// roofline: 7.23 TB/s app-effective (90.4% of 8 TB/s spec) on a 1:1 R/W stream.
// Measured policy optimum: loads ld.global.nc.cs.v8, stores st.global.wt.v8.
// R11: final combo -- ILP=2 (two v8 groups/thread, 8 loads in flight, half the
// threads) on top of the R10 policy optimum.

static constexpr float DECAY  = 0.25f;
static constexpr float THRESH = 0.5f;   // V_TH=1: mem/V_TH > 0.5 <=> mem > 0.5

struct f8 { float v[8]; };

__device__ __forceinline__ f8 ldg256_nc_cs(const float* p) {
    f8 r;
    asm volatile(
        "ld.global.nc.cs.v8.f32 {%0,%1,%2,%3,%4,%5,%6,%7}, [%8];"
        : "=f"(r.v[0]), "=f"(r.v[1]), "=f"(r.v[2]), "=f"(r.v[3]),
          "=f"(r.v[4]), "=f"(r.v[5]), "=f"(r.v[6]), "=f"(r.v[7])
        : "l"(p));
    return r;
}

__device__ __forceinline__ void stg256_wt(float* p, const f8& r) {
    asm volatile(
        "st.global.wt.v8.f32 [%0], {%1,%2,%3,%4,%5,%6,%7,%8};"
        :: "l"(p),
           "f"(r.v[0]), "f"(r.v[1]), "f"(r.v[2]), "f"(r.v[3]),
           "f"(r.v[4]), "f"(r.v[5]), "f"(r.v[6]), "f"(r.v[7])
        : "memory");
}

__device__ __forceinline__ void lif_step(float& mem, const float x, float& sp) {
    mem = fmaf(mem, DECAY, x);
    bool s = mem > THRESH;
    sp  = s ? 1.f : 0.f;
    mem = s ? 0.f : mem;
}

__device__ __forceinline__ void lif_step8(f8& mem, f8& io /* in: x, out: spike */) {
    #pragma unroll
    for (int k = 0; k < 8; ++k)
        lif_step(mem.v[k], io.v[k], io.v[k]);
}

__global__ __launch_bounds__(256)
void lif_kernel(const float* __restrict__ x, float* __restrict__ out, int n8) {
    // Two adjacent-coalesced v8 groups per thread.
    const int g0 = blockIdx.x * (blockDim.x * 2) + threadIdx.x;
    const int g1 = g0 + blockDim.x;
    if (g1 >= n8) {
        if (g0 < n8) {   // tail safety (not taken for bench shape)
            const size_t e = (size_t)g0 * 8, n = (size_t)n8 * 8;
            f8 mem; 
            #pragma unroll
            for (int k = 0; k < 8; ++k) mem.v[k] = 0.f;
            #pragma unroll
            for (int t = 0; t < 4; ++t) {
                f8 v = ldg256_nc_cs(x + (size_t)t * n + e);
                lif_step8(mem, v);
                stg256_wt(out + (size_t)t * n + e, v);
            }
        }
        return;
    }

    const size_t eA = (size_t)g0 * 8;
    const size_t eB = (size_t)g1 * 8;
    const size_t n  = (size_t)n8 * 8;        // elements per timestep

    // ---- read phase: 8 independent 256-bit nc loads in flight ----
    f8 a0 = ldg256_nc_cs(x + 0 * n + eA);
    f8 b0 = ldg256_nc_cs(x + 0 * n + eB);
    f8 a1 = ldg256_nc_cs(x + 1 * n + eA);
    f8 b1 = ldg256_nc_cs(x + 1 * n + eB);
    f8 a2 = ldg256_nc_cs(x + 2 * n + eA);
    f8 b2 = ldg256_nc_cs(x + 2 * n + eB);
    f8 a3 = ldg256_nc_cs(x + 3 * n + eA);
    f8 b3 = ldg256_nc_cs(x + 3 * n + eB);

    // ---- compute: two independent recurrence chains ----
    f8 memA, memB;
    #pragma unroll
    for (int k = 0; k < 8; ++k) { memA.v[k] = 0.f; memB.v[k] = 0.f; }
    lif_step8(memA, a0);  lif_step8(memB, b0);
    lif_step8(memA, a1);  lif_step8(memB, b1);
    lif_step8(memA, a2);  lif_step8(memB, b2);
    lif_step8(memA, a3);  lif_step8(memB, b3);

    // ---- write phase: batched 256-bit write-through stores ----
    stg256_wt(out + 0 * n + eA, a0);
    stg256_wt(out + 0 * n + eB, b0);
    stg256_wt(out + 1 * n + eA, a1);
    stg256_wt(out + 1 * n + eB, b1);
    stg256_wt(out + 2 * n + eA, a2);
    stg256_wt(out + 2 * n + eB, b2);
    stg256_wt(out + 3 * n + eA, a3);
    stg256_wt(out + 3 * n + eB, b3);
}

extern "C" void kernel_launch(void* const* d_in, const int* in_sizes, int n_in,
                              void* d_out, int out_size) {
    const float* x = (const float*)d_in[0];
    float* out = (float*)d_out;

    const int total = in_sizes[0];          // T*N = 33,554,432
    const int n = total / 4;                // N per timestep = 8,388,608
    const int n8 = n / 8;                   // v8 groups per timestep = 1,048,576

    const int threads = 256;
    const int groups_per_block = threads * 2;
    const int blocks = (n8 + groups_per_block - 1) / groups_per_block;   // 2048

    lif_kernel<<<blocks, threads>>>(x, out, n8);
}

// round 13
// speedup vs baseline: 1.0247x; 1.0247x over previous
#include <cuda_runtime.h>
#include <cstdint>

// LIF recurrence over 4 timesteps (forward value only):
//   mem = 0.25*mem + x[t]; spike = mem > 0.5; out[t] = spike; mem = spike ? 0 : mem
//
// x/out: [T=4, N=8388608] fp32. FINAL FORM (= R10, best measured: 37.12us
// kernel, 7.23 TB/s app-effective = 90.4% of HBM spec on a 1:1 R/W stream).
// Exhaustive search results:
//   - fused 1-kernel >> 2-pass split (pure-write streams run ~3.5 TB/s; 2x replay cost)
//   - 256-bit v8 ld/st, ILP=1 (ILP=2 @ regs=60 regressed 2%)
//   - loads ld.global.nc.cs (read-only, zero reuse)
//   - stores st.global.wt (> .cs > .wb: avoid L2 dirty allocate+writeback)
//   - occupancy/MLP/grid-shape knobs all neutral: limiter is DRAM bus efficiency.

static constexpr float DECAY  = 0.25f;
static constexpr float THRESH = 0.5f;   // V_TH=1: mem/V_TH > 0.5 <=> mem > 0.5

struct f8 { float v[8]; };

__device__ __forceinline__ f8 ldg256_nc_cs(const float* p) {
    f8 r;
    asm volatile(
        "ld.global.nc.cs.v8.f32 {%0,%1,%2,%3,%4,%5,%6,%7}, [%8];"
        : "=f"(r.v[0]), "=f"(r.v[1]), "=f"(r.v[2]), "=f"(r.v[3]),
          "=f"(r.v[4]), "=f"(r.v[5]), "=f"(r.v[6]), "=f"(r.v[7])
        : "l"(p));
    return r;
}

__device__ __forceinline__ void stg256_wt(float* p, const f8& r) {
    asm volatile(
        "st.global.wt.v8.f32 [%0], {%1,%2,%3,%4,%5,%6,%7,%8};"
        :: "l"(p),
           "f"(r.v[0]), "f"(r.v[1]), "f"(r.v[2]), "f"(r.v[3]),
           "f"(r.v[4]), "f"(r.v[5]), "f"(r.v[6]), "f"(r.v[7])
        : "memory");
}

__device__ __forceinline__ void lif_step(float& mem, const float x, float& sp) {
    mem = fmaf(mem, DECAY, x);
    bool s = mem > THRESH;
    sp  = s ? 1.f : 0.f;
    mem = s ? 0.f : mem;
}

__device__ __forceinline__ void lif_step8(f8& mem, f8& io /* in: x, out: spike */) {
    #pragma unroll
    for (int k = 0; k < 8; ++k)
        lif_step(mem.v[k], io.v[k], io.v[k]);
}

__global__ __launch_bounds__(256)
void lif_kernel(const float* __restrict__ x, float* __restrict__ out, int n8) {
    const int i = blockIdx.x * blockDim.x + threadIdx.x;
    if (i >= n8) return;

    const size_t e = (size_t)i * 8;          // element offset within a timestep
    const size_t n = (size_t)n8 * 8;         // elements per timestep

    // ---- read phase: 4 independent 256-bit nc loads in flight ----
    f8 v0 = ldg256_nc_cs(x + 0 * n + e);
    f8 v1 = ldg256_nc_cs(x + 1 * n + e);
    f8 v2 = ldg256_nc_cs(x + 2 * n + e);
    f8 v3 = ldg256_nc_cs(x + 3 * n + e);

    // ---- compute: sequential recurrence in registers ----
    f8 mem;
    #pragma unroll
    for (int k = 0; k < 8; ++k) mem.v[k] = 0.f;
    lif_step8(mem, v0);
    lif_step8(mem, v1);
    lif_step8(mem, v2);
    lif_step8(mem, v3);

    // ---- write phase: batched 256-bit write-through stores ----
    stg256_wt(out + 0 * n + e, v0);
    stg256_wt(out + 1 * n + e, v1);
    stg256_wt(out + 2 * n + e, v2);
    stg256_wt(out + 3 * n + e, v3);
}

extern "C" void kernel_launch(void* const* d_in, const int* in_sizes, int n_in,
                              void* d_out, int out_size) {
    const float* x = (const float*)d_in[0];
    float* out = (float*)d_out;

    const int total = in_sizes[0];          // T*N = 33,554,432
    const int n = total / 4;                // N per timestep = 8,388,608
    const int n8 = n / 8;                   // v8 groups per timestep = 1,048,576

    const int threads = 256;
    const int blocks = (n8 + threads - 1) / threads;   // 4096

    lif_kernel<<<blocks, threads>>>(x, out, n8);
}